// round 9
// baseline (speedup 1.0000x reference)
#include <cuda_runtime.h>
#include <cuda_bf16.h>
#include <math.h>

#define BATCH 65536
#define NPAIR 32768
#define DIM   256
#define FULLM 0xffffffffu

// smem: att_w1 transposed [16][512] fp32 (32768B) + pred_w1 packed bf16 (12288B)
#define SW1_FLOATS (16 * 512)
#define SWP_HALFS  (8 * 3 * 256)
#define SMEM_BYTES (SW1_FLOATS * 4 + SWP_HALFS * 2)   // 45056 B -> 4 blocks/SM = 180KB

typedef unsigned long long u64;

// ---- packed f32x2 (FFMA2) helpers ----
__device__ __forceinline__ u64 ffma2(u64 a, u64 b, u64 c) {
    u64 d; asm("fma.rn.f32x2 %0,%1,%2,%3;" : "=l"(d) : "l"(a), "l"(b), "l"(c)); return d;
}
__device__ __forceinline__ u64 fadd2(u64 a, u64 b) {
    u64 d; asm("add.rn.f32x2 %0,%1,%2;" : "=l"(d) : "l"(a), "l"(b)); return d;
}
__device__ __forceinline__ u64 fmul2(u64 a, u64 b) {
    u64 d; asm("mul.rn.f32x2 %0,%1,%2;" : "=l"(d) : "l"(a), "l"(b)); return d;
}
__device__ __forceinline__ u64 dup2(float x) {
    u64 r; asm("mov.b64 %0,{%1,%1};" : "=l"(r) : "f"(x)); return r;
}
__device__ __forceinline__ float hadd2(u64 p) {
    float x, y; asm("mov.b64 {%0,%1},%2;" : "=f"(x), "=f"(y) : "l"(p));
    return x + y;
}
__device__ __forceinline__ u64 bf2f2(unsigned int u) {
    unsigned int lo = u << 16, hi = u & 0xffff0000u;
    u64 r; asm("mov.b64 %0,{%1,%2};" : "=l"(r) : "r"(lo), "r"(hi)); return r;
}
__device__ __forceinline__ void pfl2(const void* p) {
    asm volatile("prefetch.global.L2 [%0];" :: "l"(p));
}

// SEL-free fold over 8 values: slot i holds partial of value (i ^ (lane&7));
// returns full 32-lane sum of value (lane&7).
__device__ __forceinline__ float fold8x(float* A) {
    #pragma unroll
    for (int d = 4; d >= 1; d >>= 1)
        #pragma unroll
        for (int i = 0; i < d; i++)
            A[i] += __shfl_xor_sync(FULLM, A[i + d], d);
    float v = A[0];
    v += __shfl_xor_sync(FULLM, v, 8);
    v += __shfl_xor_sync(FULLM, v, 16);
    return v;
}

__device__ __forceinline__ void perm4i(const int* in, int* out, int p) {
    int t0 = (p & 1) ? in[1] : in[0];
    int t1 = (p & 1) ? in[0] : in[1];
    int t2 = (p & 1) ? in[3] : in[2];
    int t3 = (p & 1) ? in[2] : in[3];
    out[0] = (p & 2) ? t2 : t0;
    out[1] = (p & 2) ? t3 : t1;
    out[2] = (p & 2) ? t0 : t2;
    out[3] = (p & 2) ? t1 : t3;
}
__device__ __forceinline__ void perm4f(const float* in, float* out, int p) {
    float t0 = (p & 1) ? in[1] : in[0];
    float t1 = (p & 1) ? in[0] : in[1];
    float t2 = (p & 1) ? in[3] : in[2];
    float t3 = (p & 1) ? in[2] : in[3];
    out[0] = (p & 2) ? t2 : t0;
    out[1] = (p & 2) ? t3 : t1;
    out[2] = (p & 2) ? t0 : t2;
    out[3] = (p & 2) ? t1 : t3;
}

__global__ __launch_bounds__(128, 4)
void agree_kernel(
    const int*   __restrict__ group_inputs,
    const int*   __restrict__ item_inputs,
    const int*   __restrict__ group_members,
    const float* __restrict__ user_emb,
    const float* __restrict__ item_emb,
    const float* __restrict__ group_emb,
    const float* __restrict__ att_w1,
    const float* __restrict__ att_b1,
    const float* __restrict__ att_w2,
    const float* __restrict__ att_b2,
    const float* __restrict__ cls_w,
    const float* __restrict__ cls_b,
    const float* __restrict__ pred_w1,
    const float* __restrict__ pred_b1,
    const float* __restrict__ pred_w2,
    const float* __restrict__ pred_b2,
    float*       __restrict__ out)
{
    extern __shared__ float sm[];
    float* sw1 = sm;                                        // [16][512] fp32
    __nv_bfloat16* swp = (__nv_bfloat16*)(sm + SW1_FLOATS); // packed bf16

    const int tid = threadIdx.x;

    for (int i = tid; i < 512 * 16; i += blockDim.x) {
        int d = i >> 4, f = i & 15;
        sw1[f * 512 + d] = att_w1[i];
    }
    for (int i = tid; i < SWP_HALFS; i += blockDim.x) {
        int k   = i / 768;
        int rem = i - k * 768;
        int r   = rem >> 8;
        int qq  = rem & 255;
        int ln  = qq >> 3;
        int ii  = qq & 7;
        int j   = r * 256 + ((ii & 4) ? 128 : 0) + 4 * ln + (ii & 3);
        swp[i] = __float2bfloat16(pred_w1[j * 8 + k]);
    }
    __syncthreads();

    const int lane  = tid & 31;
    const int gwarp = blockIdx.x * 4 + (tid >> 5);
    const int nwarp = gridDim.x * 4;

    const int q1 = lane & 1;          // f-parity permutation
    const int p2 = (lane >> 1) & 3;   // member permutation
    const int l7 = lane & 7;

    for (int pp = gwarp; pp < NPAIR; pp += nwarp) {
        // current ids (L1-hot: last iteration's pipelined loads touched them)
        const int gidA = group_inputs[2 * pp];
        const int gidB = group_inputs[2 * pp + 1];
        const int iidA = item_inputs[2 * pp];
        const int iidB = item_inputs[2 * pp + 1];
        const int4 mA = *(const int4*)(group_members + gidA * 4);
        const int4 mB = *(const int4*)(group_members + gidB * 4);

        // permute member ids: pmem slot s holds member (s ^ p2)
        int mpA[4], mpB[4];
        {
            int rawA[4] = {mA.x, mA.y, mA.z, mA.w};
            int rawB[4] = {mB.x, mB.y, mB.z, mB.w};
            perm4i(rawA, mpA, p2);
            perm4i(rawB, mpB, p2);
        }

        // gather rows (L2-warm from last iteration's prefetch)
        u64 pmem[2][4][4], pit[2][4];
        #pragma unroll
        for (int s = 0; s < 4; s++) {
            const ulonglong2* rA = (const ulonglong2*)(user_emb + (size_t)mpA[s] * DIM);
            const ulonglong2* rB = (const ulonglong2*)(user_emb + (size_t)mpB[s] * DIM);
            ulonglong2 a0 = rA[lane], a1 = rA[32 + lane];
            ulonglong2 c0 = rB[lane], c1 = rB[32 + lane];
            pmem[0][s][0] = a0.x; pmem[0][s][1] = a0.y; pmem[0][s][2] = a1.x; pmem[0][s][3] = a1.y;
            pmem[1][s][0] = c0.x; pmem[1][s][1] = c0.y; pmem[1][s][2] = c1.x; pmem[1][s][3] = c1.y;
        }
        {
            const ulonglong2* iA = (const ulonglong2*)(item_emb + (size_t)iidA * DIM);
            const ulonglong2* iB = (const ulonglong2*)(item_emb + (size_t)iidB * DIM);
            ulonglong2 a0 = iA[lane], a1 = iA[32 + lane];
            ulonglong2 c0 = iB[lane], c1 = iB[32 + lane];
            pit[0][0] = a0.x; pit[0][1] = a0.y; pit[0][2] = a1.x; pit[0][3] = a1.y;
            pit[1][0] = c0.x; pit[1][1] = c0.y; pit[1][2] = c1.x; pit[1][3] = c1.y;
        }

        // early-issue next iteration's index chain (resolves under attention)
        const int ppn = pp + nwarp;
        const bool hn = ppn < NPAIR;
        const int bn = hn ? 2 * ppn : 2 * pp;
        const int gidAn = group_inputs[bn];
        const int gidBn = group_inputs[bn + 1];
        const int iidAn = item_inputs[bn];
        const int iidBn = item_inputs[bn + 1];
        const int4 mAn = *(const int4*)(group_members + gidAn * 4);
        const int4 mBn = *(const int4*)(group_members + gidBn * 4);

        // ---- attention MLP: 8 chunks of 2 f, FFMA2, XOR-permuted slots ----
        float logit_loc[2] = {0.f, 0.f};
        #pragma unroll
        for (int c = 0; c < 8; c++) {
            float A0[8], A1[8];
            #pragma unroll
            for (int fi = 0; fi < 2; fi++) {
                // slot (s*2+fi) uses weight row f = c*2 + (fi ^ q1)
                const float* wrow = sw1 + c * 1024 + (((fi ^ q1)) << 9) + 4 * lane;
                ulonglong2 wm0 = *(const ulonglong2*)(wrow);
                ulonglong2 wm1 = *(const ulonglong2*)(wrow + 128);
                ulonglong2 wi0 = *(const ulonglong2*)(wrow + 256);
                ulonglong2 wi1 = *(const ulonglong2*)(wrow + 384);

                u64 t0 = fmul2(pit[0][0], wi0.x);
                t0 = ffma2(pit[0][1], wi0.y, t0);
                t0 = ffma2(pit[0][2], wi1.x, t0);
                t0 = ffma2(pit[0][3], wi1.y, t0);
                u64 t1 = fmul2(pit[1][0], wi0.x);
                t1 = ffma2(pit[1][1], wi0.y, t1);
                t1 = ffma2(pit[1][2], wi1.x, t1);
                t1 = ffma2(pit[1][3], wi1.y, t1);

                #pragma unroll
                for (int s = 0; s < 4; s++) {
                    u64 a = t0;
                    a = ffma2(pmem[0][s][0], wm0.x, a);
                    a = ffma2(pmem[0][s][1], wm0.y, a);
                    a = ffma2(pmem[0][s][2], wm1.x, a);
                    a = ffma2(pmem[0][s][3], wm1.y, a);
                    A0[s * 2 + fi] = hadd2(a);
                    u64 b = t1;
                    b = ffma2(pmem[1][s][0], wm0.x, b);
                    b = ffma2(pmem[1][s][1], wm0.y, b);
                    b = ffma2(pmem[1][s][2], wm1.x, b);
                    b = ffma2(pmem[1][s][3], wm1.y, b);
                    A1[s * 2 + fi] = hadd2(b);
                }
            }
            // fold -> lane holds value (lane&7): s = p2, f = c*2 + q1
            const float bc = __ldg(att_b1 + c * 2 + q1);
            const float wc = __ldg(att_w2 + c * 2 + q1);
            {
                float r0 = fold8x(A0);
                float cv = fmaxf(r0 + bc, 0.f) * wc;
                cv += __shfl_xor_sync(FULLM, cv, 1);   // sum f-pair of chunk
                logit_loc[0] += cv;
            }
            {
                float r1 = fold8x(A1);
                float cv = fmaxf(r1 + bc, 0.f) * wc;
                cv += __shfl_xor_sync(FULLM, cv, 1);
                logit_loc[1] += cv;
            }
        }
        {
            const float b2v = __ldg(att_b2);
            logit_loc[0] += b2v;
            logit_loc[1] += b2v;
        }

        // prefetch next iteration's embedding rows into L2
        if (hn) {
            int mn[8] = {mAn.x, mAn.y, mAn.z, mAn.w, mBn.x, mBn.y, mBn.z, mBn.w};
            #pragma unroll
            for (int s = 0; s < 8; s++) {
                const float* r = user_emb + (size_t)mn[s] * DIM + 4 * lane;
                pfl2(r); pfl2(r + 128);
            }
            const float* ra = item_emb + (size_t)iidAn * DIM + 4 * lane;
            const float* rb = item_emb + (size_t)iidBn * DIM + 4 * lane;
            pfl2(ra); pfl2(ra + 128);
            pfl2(rb); pfl2(rb + 128);
            const float* ga = group_emb + (size_t)gidAn * DIM + 4 * lane;
            const float* gb = group_emb + (size_t)gidBn * DIM + 4 * lane;
            pfl2(ga); pfl2(ga + 128);
            pfl2(gb); pfl2(gb + 128);
        }

        // softmax / argmax / classifier per element (lane s*2 holds member s)
        float wt[2][4];
        int   pc[2];
        float cwp[2][4];
        #pragma unroll
        for (int e = 0; e < 2; e++) {
            float logit[4];
            #pragma unroll
            for (int s = 0; s < 4; s++)
                logit[s] = __shfl_sync(FULLM, logit_loc[e], s * 2);

            float mx = logit[0]; int ix = 0;
            #pragma unroll
            for (int s = 1; s < 4; s++)
                if (logit[s] > mx) { mx = logit[s]; ix = s; }

            float ev[4], sum = 0.f;
            #pragma unroll
            for (int s = 0; s < 4; s++) { ev[s] = expf(logit[s] - mx); sum += ev[s]; }
            float inv = 1.f / sum;
            #pragma unroll
            for (int s = 0; s < 4; s++) wt[e][s] = ev[s] * inv;

            float s0 = inv * __ldg(cls_w) + __ldg(cls_b);       // wt[ix] == inv exactly
            float s1 = inv * __ldg(cls_w + 1) + __ldg(cls_b + 1);
            pc[e] = (s1 > s0) ? 1 : 0;
            float cw[4];
            #pragma unroll
            for (int s = 0; s < 4; s++)
                cw[s] = pc[e] ? ((s == ix) ? 1.f : 0.f) : wt[e][s];
            perm4f(cw, cwp[e], p2);   // cwp[s] = cw[s ^ p2] matches pmem slot s
        }

        // ---- epilogue packed: gv = sum_s cwp*mem + grp (el recomputed later) ----
        u64 pgv[2][4];
        {
            const ulonglong2* gA = (const ulonglong2*)(group_emb + (size_t)gidA * DIM);
            const ulonglong2* gB = (const ulonglong2*)(group_emb + (size_t)gidB * DIM);
            #pragma unroll
            for (int e = 0; e < 2; e++) {
                u64 c0 = dup2(cwp[e][0]), c1 = dup2(cwp[e][1]);
                u64 c2 = dup2(cwp[e][2]), c3 = dup2(cwp[e][3]);
                const ulonglong2* grow = (e == 0) ? gA : gB;
                ulonglong2 g0 = grow[lane], g1 = grow[32 + lane];
                u64 grp[4] = {g0.x, g0.y, g1.x, g1.y};
                #pragma unroll
                for (int j = 0; j < 4; j++) {
                    u64 t = fmul2(pmem[e][0][j], c0);
                    t = ffma2(pmem[e][1][j], c1, t);
                    t = ffma2(pmem[e][2][j], c2, t);
                    t = ffma2(pmem[e][3][j], c3, t);
                    pgv[e][j] = fadd2(t, grp[j]);
                }
            }
        }

        // ---- prediction MLP: FFMA2, slot k holds value (k ^ l7), el on the fly ----
        float A20[8], A21[8];
        #pragma unroll
        for (int k = 0; k < 8; k++) {
            const int kk = k ^ l7;
            u64 a0 = 0ull, a1 = 0ull;
            #pragma unroll
            for (int r = 0; r < 3; r++) {
                uint4 u = *(const uint4*)(swp + (kk * 3 + r) * 256 + lane * 8);
                u64 w0 = bf2f2(u.x), w1 = bf2f2(u.y), w2 = bf2f2(u.z), w3 = bf2f2(u.w);
                #pragma unroll
                for (int e = 0; e < 2; e++) {
                    u64 v0, v1, v2, v3;
                    if (r == 0) {        // el = gv * it, recomputed
                        v0 = fmul2(pgv[e][0], pit[e][0]);
                        v1 = fmul2(pgv[e][1], pit[e][1]);
                        v2 = fmul2(pgv[e][2], pit[e][2]);
                        v3 = fmul2(pgv[e][3], pit[e][3]);
                    } else if (r == 1) {
                        v0 = pgv[e][0]; v1 = pgv[e][1]; v2 = pgv[e][2]; v3 = pgv[e][3];
                    } else {
                        v0 = pit[e][0]; v1 = pit[e][1]; v2 = pit[e][2]; v3 = pit[e][3];
                    }
                    u64& a = (e == 0) ? a0 : a1;
                    a = ffma2(v0, w0, a);
                    a = ffma2(v1, w1, a);
                    a = ffma2(v2, w2, a);
                    a = ffma2(v3, w3, a);
                }
            }
            A20[k] = hadd2(a0);
            A21[k] = hadd2(a1);
        }

        float y[2];
        #pragma unroll
        for (int e = 0; e < 2; e++) {
            float v = fold8x(e == 0 ? A20 : A21);   // full acc for k = lane&7
            float hz = fmaxf(v + __ldg(pred_b1 + l7), 0.f) * __ldg(pred_w2 + l7);
            hz += __shfl_xor_sync(FULLM, hz, 1);
            hz += __shfl_xor_sync(FULLM, hz, 2);
            hz += __shfl_xor_sync(FULLM, hz, 4);
            float z = hz + __ldg(pred_b2);
            y[e] = 1.f / (1.f + expf(-z));
        }

        if (lane < 2) {
            const int e = lane;
            const int b = 2 * pp + e;
            out[b] = y[e];
            *(float4*)(out + BATCH + 4 * b) = make_float4(wt[e][0], wt[e][1], wt[e][2], wt[e][3]);
            out[5 * BATCH + b] = (float)pc[e];
        }
    }
}

extern "C" void kernel_launch(void* const* d_in, const int* in_sizes, int n_in,
                              void* d_out, int out_size)
{
    (void)in_sizes; (void)n_in; (void)out_size;
    cudaFuncSetAttribute(agree_kernel,
                         cudaFuncAttributeMaxDynamicSharedMemorySize, SMEM_BYTES);
    agree_kernel<<<592, 128, SMEM_BYTES>>>(
        (const int*)d_in[0],  (const int*)d_in[1],  (const int*)d_in[2],
        (const float*)d_in[3], (const float*)d_in[4], (const float*)d_in[5],
        (const float*)d_in[6], (const float*)d_in[7], (const float*)d_in[8],
        (const float*)d_in[9], (const float*)d_in[10], (const float*)d_in[11],
        (const float*)d_in[12], (const float*)d_in[13], (const float*)d_in[14],
        (const float*)d_in[15],
        (float*)d_out);
}

// round 10
// speedup vs baseline: 1.1362x; 1.1362x over previous
#include <cuda_runtime.h>
#include <cuda_bf16.h>
#include <math.h>

#define BATCH 65536
#define NPAIR 32768
#define DIM   256
#define FULLM 0xffffffffu

// smem: att_w1 transposed [16][512] fp32 (32768B) + pred_w1 packed bf16 (12288B)
#define SW1_FLOATS (16 * 512)
#define SWP_HALFS  (8 * 3 * 256)
#define SMEM_BYTES (SW1_FLOATS * 4 + SWP_HALFS * 2)   // 45056 B

typedef unsigned long long u64;

// ---- packed f32x2 (FFMA2) helpers ----
__device__ __forceinline__ u64 ffma2(u64 a, u64 b, u64 c) {
    u64 d; asm("fma.rn.f32x2 %0,%1,%2,%3;" : "=l"(d) : "l"(a), "l"(b), "l"(c)); return d;
}
__device__ __forceinline__ u64 fadd2(u64 a, u64 b) {
    u64 d; asm("add.rn.f32x2 %0,%1,%2;" : "=l"(d) : "l"(a), "l"(b)); return d;
}
__device__ __forceinline__ u64 fmul2(u64 a, u64 b) {
    u64 d; asm("mul.rn.f32x2 %0,%1,%2;" : "=l"(d) : "l"(a), "l"(b)); return d;
}
__device__ __forceinline__ u64 dup2(float x) {
    u64 r; asm("mov.b64 %0,{%1,%1};" : "=l"(r) : "f"(x)); return r;
}
__device__ __forceinline__ float hadd2(u64 p) {
    float x, y; asm("mov.b64 {%0,%1},%2;" : "=f"(x), "=f"(y) : "l"(p));
    return x + y;
}
__device__ __forceinline__ u64 bf2f2(unsigned int u) {
    unsigned int lo = u << 16, hi = u & 0xffff0000u;
    u64 r; asm("mov.b64 %0,{%1,%2};" : "=l"(r) : "r"(lo), "r"(hi)); return r;
}
__device__ __forceinline__ void pfl2(const void* p) {
    asm volatile("prefetch.global.L2 [%0];" :: "l"(p));
}

// SEL-free folds (slot i holds value i ^ (lane&mask))
__device__ __forceinline__ float fold16x(float* A) {
    #pragma unroll
    for (int d = 8; d >= 1; d >>= 1)
        #pragma unroll
        for (int i = 0; i < d; i++)
            A[i] += __shfl_xor_sync(FULLM, A[i + d], d);
    float v = A[0];
    v += __shfl_xor_sync(FULLM, v, 16);
    return v;
}
__device__ __forceinline__ float fold8x(float* A) {
    #pragma unroll
    for (int d = 4; d >= 1; d >>= 1)
        #pragma unroll
        for (int i = 0; i < d; i++)
            A[i] += __shfl_xor_sync(FULLM, A[i + d], d);
    float v = A[0];
    v += __shfl_xor_sync(FULLM, v, 8);
    v += __shfl_xor_sync(FULLM, v, 16);
    return v;
}

__device__ __forceinline__ void perm4i(const int* in, int* out, int p) {
    int t0 = (p & 1) ? in[1] : in[0];
    int t1 = (p & 1) ? in[0] : in[1];
    int t2 = (p & 1) ? in[3] : in[2];
    int t3 = (p & 1) ? in[2] : in[3];
    out[0] = (p & 2) ? t2 : t0;
    out[1] = (p & 2) ? t3 : t1;
    out[2] = (p & 2) ? t0 : t2;
    out[3] = (p & 2) ? t1 : t3;
}
__device__ __forceinline__ void perm4f(const float* in, float* out, int p) {
    float t0 = (p & 1) ? in[1] : in[0];
    float t1 = (p & 1) ? in[0] : in[1];
    float t2 = (p & 1) ? in[3] : in[2];
    float t3 = (p & 1) ? in[2] : in[3];
    out[0] = (p & 2) ? t2 : t0;
    out[1] = (p & 2) ? t3 : t1;
    out[2] = (p & 2) ? t0 : t2;
    out[3] = (p & 2) ? t1 : t3;
}

__global__ __launch_bounds__(128, 3)
void agree_kernel(
    const int*   __restrict__ group_inputs,
    const int*   __restrict__ item_inputs,
    const int*   __restrict__ group_members,
    const float* __restrict__ user_emb,
    const float* __restrict__ item_emb,
    const float* __restrict__ group_emb,
    const float* __restrict__ att_w1,
    const float* __restrict__ att_b1,
    const float* __restrict__ att_w2,
    const float* __restrict__ att_b2,
    const float* __restrict__ cls_w,
    const float* __restrict__ cls_b,
    const float* __restrict__ pred_w1,
    const float* __restrict__ pred_b1,
    const float* __restrict__ pred_w2,
    const float* __restrict__ pred_b2,
    float*       __restrict__ out)
{
    extern __shared__ float sm[];
    float* sw1 = sm;                                        // [16][512] fp32
    __nv_bfloat16* swp = (__nv_bfloat16*)(sm + SW1_FLOATS); // packed bf16

    const int tid = threadIdx.x;

    for (int i = tid; i < 512 * 16; i += blockDim.x) {
        int d = i >> 4, f = i & 15;
        sw1[f * 512 + d] = att_w1[i];
    }
    for (int i = tid; i < SWP_HALFS; i += blockDim.x) {
        int k   = i / 768;
        int rem = i - k * 768;
        int r   = rem >> 8;
        int qq  = rem & 255;
        int ln  = qq >> 3;
        int ii  = qq & 7;
        int j   = r * 256 + ((ii & 4) ? 128 : 0) + 4 * ln + (ii & 3);
        swp[i] = __float2bfloat16(pred_w1[j * 8 + k]);
    }
    __syncthreads();

    const int lane  = tid & 31;
    const int gwarp = blockIdx.x * 4 + (tid >> 5);
    const int nwarp = gridDim.x * 4;

    const int q  = lane & 3;
    const int p  = (lane >> 2) & 3;
    const int l7 = lane & 7;
    const int qs = q << 9;

    float b1c[4], w2c[4];
    #pragma unroll
    for (int c = 0; c < 4; c++) {
        b1c[c] = __ldg(att_b1 + c * 4 + q);
        w2c[c] = __ldg(att_w2 + c * 4 + q);
    }
    const float pbk  = __ldg(pred_b1 + l7);
    const float pwk  = __ldg(pred_w2 + l7);
    const float b2v  = __ldg(att_b2);
    const float clw0 = __ldg(cls_w), clw1 = __ldg(cls_w + 1);
    const float clb0 = __ldg(cls_b), clb1 = __ldg(cls_b + 1);
    const float pb2  = __ldg(pred_b2);

    // ---- software-pipelined index chain: prologue load for first iteration ----
    int gidA = group_inputs[2 * gwarp];
    int gidB = group_inputs[2 * gwarp + 1];
    int iidA = item_inputs[2 * gwarp];
    int iidB = item_inputs[2 * gwarp + 1];
    int4 mA = *(const int4*)(group_members + gidA * 4);
    int4 mB = *(const int4*)(group_members + gidB * 4);

    for (int pp = gwarp; pp < NPAIR; pp += nwarp) {
        // permute current member ids: slot s holds member (s ^ p)
        int mpA[4], mpB[4];
        {
            int rawA[4] = {mA.x, mA.y, mA.z, mA.w};
            int rawB[4] = {mB.x, mB.y, mB.z, mB.w};
            perm4i(rawA, mpA, p);
            perm4i(rawB, mpB, p);
        }

        // gather current rows (addresses warm in L2 from last iteration's prefetch)
        u64 pmem[2][4][4], pit[2][4];
        #pragma unroll
        for (int s = 0; s < 4; s++) {
            const ulonglong2* rA = (const ulonglong2*)(user_emb + (size_t)mpA[s] * DIM);
            const ulonglong2* rB = (const ulonglong2*)(user_emb + (size_t)mpB[s] * DIM);
            ulonglong2 a0 = rA[lane], a1 = rA[32 + lane];
            ulonglong2 c0 = rB[lane], c1 = rB[32 + lane];
            pmem[0][s][0] = a0.x; pmem[0][s][1] = a0.y; pmem[0][s][2] = a1.x; pmem[0][s][3] = a1.y;
            pmem[1][s][0] = c0.x; pmem[1][s][1] = c0.y; pmem[1][s][2] = c1.x; pmem[1][s][3] = c1.y;
        }
        {
            const ulonglong2* iA = (const ulonglong2*)(item_emb + (size_t)iidA * DIM);
            const ulonglong2* iB = (const ulonglong2*)(item_emb + (size_t)iidB * DIM);
            ulonglong2 a0 = iA[lane], a1 = iA[32 + lane];
            ulonglong2 c0 = iB[lane], c1 = iB[32 + lane];
            pit[0][0] = a0.x; pit[0][1] = a0.y; pit[0][2] = a1.x; pit[0][3] = a1.y;
            pit[1][0] = c0.x; pit[1][1] = c0.y; pit[1][2] = c1.x; pit[1][3] = c1.y;
        }

        // early-issue next iteration's index chain (resolves under attention)
        const int ppn = pp + nwarp;
        const bool hn  = ppn < NPAIR;
        const int bn  = hn ? 2 * ppn : 2 * pp;
        int gidAn = group_inputs[bn];
        int gidBn = group_inputs[bn + 1];
        int iidAn = item_inputs[bn];
        int iidBn = item_inputs[bn + 1];
        int4 mAn = *(const int4*)(group_members + gidAn * 4);
        int4 mBn = *(const int4*)(group_members + gidBn * 4);

        // ---- attention MLP: FFMA2 over dim pairs, XOR-permuted slots ----
        float logit_loc[2] = {b2v, b2v};
        #pragma unroll
        for (int c = 0; c < 4; c++) {
            float A0[16], A1[16];
            #pragma unroll
            for (int fi = 0; fi < 4; fi++) {
                const float* wrow = sw1 + c * 2048 + ((fi << 9) ^ qs) + 4 * lane;
                ulonglong2 wm0 = *(const ulonglong2*)(wrow);
                ulonglong2 wm1 = *(const ulonglong2*)(wrow + 128);
                ulonglong2 wi0 = *(const ulonglong2*)(wrow + 256);
                ulonglong2 wi1 = *(const ulonglong2*)(wrow + 384);

                u64 t0 = fmul2(pit[0][0], wi0.x);
                t0 = ffma2(pit[0][1], wi0.y, t0);
                t0 = ffma2(pit[0][2], wi1.x, t0);
                t0 = ffma2(pit[0][3], wi1.y, t0);
                u64 t1 = fmul2(pit[1][0], wi0.x);
                t1 = ffma2(pit[1][1], wi0.y, t1);
                t1 = ffma2(pit[1][2], wi1.x, t1);
                t1 = ffma2(pit[1][3], wi1.y, t1);

                #pragma unroll
                for (int s = 0; s < 4; s++) {
                    u64 a = t0;
                    a = ffma2(pmem[0][s][0], wm0.x, a);
                    a = ffma2(pmem[0][s][1], wm0.y, a);
                    a = ffma2(pmem[0][s][2], wm1.x, a);
                    a = ffma2(pmem[0][s][3], wm1.y, a);
                    A0[s * 4 + fi] = hadd2(a);
                    u64 b = t1;
                    b = ffma2(pmem[1][s][0], wm0.x, b);
                    b = ffma2(pmem[1][s][1], wm0.y, b);
                    b = ffma2(pmem[1][s][2], wm1.x, b);
                    b = ffma2(pmem[1][s][3], wm1.y, b);
                    A1[s * 4 + fi] = hadd2(b);
                }
            }
            {
                float r0 = fold16x(A0);
                float cv = fmaxf(r0 + b1c[c], 0.f) * w2c[c];
                cv += __shfl_xor_sync(FULLM, cv, 1);
                cv += __shfl_xor_sync(FULLM, cv, 2);
                logit_loc[0] += cv;
            }
            {
                float r1 = fold16x(A1);
                float cv = fmaxf(r1 + b1c[c], 0.f) * w2c[c];
                cv += __shfl_xor_sync(FULLM, cv, 1);
                cv += __shfl_xor_sync(FULLM, cv, 2);
                logit_loc[1] += cv;
            }
        }

        // prefetch next iteration's embedding rows into L2 (next ids arrived by now)
        if (hn) {
            int mn[8] = {mAn.x, mAn.y, mAn.z, mAn.w, mBn.x, mBn.y, mBn.z, mBn.w};
            #pragma unroll
            for (int s = 0; s < 8; s++) {
                const float* r = user_emb + (size_t)mn[s] * DIM + 4 * lane;
                pfl2(r); pfl2(r + 128);
            }
            const float* ra = item_emb + (size_t)iidAn * DIM + 4 * lane;
            const float* rb = item_emb + (size_t)iidBn * DIM + 4 * lane;
            pfl2(ra); pfl2(ra + 128);
            pfl2(rb); pfl2(rb + 128);
            const float* ga = group_emb + (size_t)gidAn * DIM + 4 * lane;
            const float* gb = group_emb + (size_t)gidBn * DIM + 4 * lane;
            pfl2(ga); pfl2(ga + 128);
            pfl2(gb); pfl2(gb + 128);
        }

        // softmax / argmax / classifier per element (lane s*4 holds member s)
        float wt[2][4];
        int   pc[2];
        float cwp[2][4];
        #pragma unroll
        for (int e = 0; e < 2; e++) {
            float logit[4];
            #pragma unroll
            for (int s = 0; s < 4; s++)
                logit[s] = __shfl_sync(FULLM, logit_loc[e], s * 4);

            float mx = logit[0]; int ix = 0;
            #pragma unroll
            for (int s = 1; s < 4; s++)
                if (logit[s] > mx) { mx = logit[s]; ix = s; }

            float ev[4], sum = 0.f;
            #pragma unroll
            for (int s = 0; s < 4; s++) { ev[s] = __expf(logit[s] - mx); sum += ev[s]; }
            float inv = 1.f / sum;
            #pragma unroll
            for (int s = 0; s < 4; s++) wt[e][s] = ev[s] * inv;

            float s0 = inv * clw0 + clb0;   // __expf(0)==1 exactly, so wt[ix] == inv
            float s1 = inv * clw1 + clb1;
            pc[e] = (s1 > s0) ? 1 : 0;
            float cw[4];
            #pragma unroll
            for (int s = 0; s < 4; s++)
                cw[s] = pc[e] ? ((s == ix) ? 1.f : 0.f) : wt[e][s];
            perm4f(cw, cwp[e], p);
        }

        // ---- epilogue packed: g = sum_s cwp*mem + grp ; el = g*it ----
        u64 pgv[2][4], pel[2][4];
        {
            const ulonglong2* gA = (const ulonglong2*)(group_emb + (size_t)gidA * DIM);
            const ulonglong2* gB = (const ulonglong2*)(group_emb + (size_t)gidB * DIM);
            #pragma unroll
            for (int e = 0; e < 2; e++) {
                u64 c0 = dup2(cwp[e][0]), c1 = dup2(cwp[e][1]);
                u64 c2 = dup2(cwp[e][2]), c3 = dup2(cwp[e][3]);
                const ulonglong2* grow = (e == 0) ? gA : gB;
                ulonglong2 g0 = grow[lane], g1 = grow[32 + lane];
                u64 grp[4] = {g0.x, g0.y, g1.x, g1.y};
                #pragma unroll
                for (int j = 0; j < 4; j++) {
                    u64 t = fmul2(pmem[e][0][j], c0);
                    t = ffma2(pmem[e][1][j], c1, t);
                    t = ffma2(pmem[e][2][j], c2, t);
                    t = ffma2(pmem[e][3][j], c3, t);
                    t = fadd2(t, grp[j]);
                    pgv[e][j] = t;
                    pel[e][j] = fmul2(t, pit[e][j]);
                }
            }
        }

        // ---- prediction MLP: FFMA2, slot k holds value (k ^ l7) ----
        float A20[8], A21[8];
        #pragma unroll
        for (int k = 0; k < 8; k++) {
            const int kk = k ^ l7;
            u64 a0 = 0ull, a1 = 0ull;
            #pragma unroll
            for (int r = 0; r < 3; r++) {
                const u64* v0 = (r == 0) ? pel[0] : (r == 1) ? pgv[0] : pit[0];
                const u64* v1 = (r == 0) ? pel[1] : (r == 1) ? pgv[1] : pit[1];
                uint4 u = *(const uint4*)(swp + (kk * 3 + r) * 256 + lane * 8);
                u64 w0 = bf2f2(u.x), w1 = bf2f2(u.y), w2 = bf2f2(u.z), w3 = bf2f2(u.w);
                a0 = ffma2(v0[0], w0, a0);
                a0 = ffma2(v0[1], w1, a0);
                a0 = ffma2(v0[2], w2, a0);
                a0 = ffma2(v0[3], w3, a0);
                a1 = ffma2(v1[0], w0, a1);
                a1 = ffma2(v1[1], w1, a1);
                a1 = ffma2(v1[2], w2, a1);
                a1 = ffma2(v1[3], w3, a1);
            }
            A20[k] = hadd2(a0);
            A21[k] = hadd2(a1);
        }

        float y[2];
        #pragma unroll
        for (int e = 0; e < 2; e++) {
            float v = fold8x(e == 0 ? A20 : A21);
            float hz = fmaxf(v + pbk, 0.f) * pwk;
            hz += __shfl_xor_sync(FULLM, hz, 1);
            hz += __shfl_xor_sync(FULLM, hz, 2);
            hz += __shfl_xor_sync(FULLM, hz, 4);
            float z = hz + pb2;
            y[e] = 1.f / (1.f + __expf(-z));
        }

        if (lane < 2) {
            const int e = lane;
            const int b = 2 * pp + e;
            out[b] = y[e];
            *(float4*)(out + BATCH + 4 * b) = make_float4(wt[e][0], wt[e][1], wt[e][2], wt[e][3]);
            out[5 * BATCH + b] = (float)pc[e];
        }

        // rotate pipelined indices
        gidA = gidAn; gidB = gidBn; iidA = iidAn; iidB = iidBn;
        mA = mAn; mB = mBn;
    }
}

extern "C" void kernel_launch(void* const* d_in, const int* in_sizes, int n_in,
                              void* d_out, int out_size)
{
    (void)in_sizes; (void)n_in; (void)out_size;
    cudaFuncSetAttribute(agree_kernel,
                         cudaFuncAttributeMaxDynamicSharedMemorySize, SMEM_BYTES);
    agree_kernel<<<444, 128, SMEM_BYTES>>>(
        (const int*)d_in[0],  (const int*)d_in[1],  (const int*)d_in[2],
        (const float*)d_in[3], (const float*)d_in[4], (const float*)d_in[5],
        (const float*)d_in[6], (const float*)d_in[7], (const float*)d_in[8],
        (const float*)d_in[9], (const float*)d_in[10], (const float*)d_in[11],
        (const float*)d_in[12], (const float*)d_in[13], (const float*)d_in[14],
        (const float*)d_in[15],
        (float*)d_out);
}